// round 16
// baseline (speedup 1.0000x reference)
#include <cuda_runtime.h>
#include <cuda_fp16.h>
#include <math.h>
#include <stdint.h>

#define B_  32
#define N_  1024
#define C_  1024
#define H_  16
#define HD_ 64
#define TOKENS (B_ * N_)        // 32768
#define TOKSTRIDE 3072

// Scratch (static device globals; no runtime allocation)
__device__ __half g_xh[(size_t)TOKENS * C_];           // fp16 x
__device__ __half g_wqkvh[(size_t)C_ * 3 * C_];        // fp16 qkv_w [1024][3072]
__device__ __half g_wprojh[(size_t)C_ * C_];           // fp16 proj_w [1024][1024]
__device__ __half g_qkvh[(size_t)TOKENS * TOKSTRIDE];  // fp16 q(roped)/k(roped)/v
__device__ __half g_attnh[(size_t)TOKENS * C_];        // fp16 attention output
__device__ float2 g_ropetab[(size_t)N_ * HD_];         // (cos, sin) per (n, c)

// ---------------------------------------------------------------------------
// Helpers
// ---------------------------------------------------------------------------
__device__ __forceinline__ void ldm_x4(uint32_t* r, const void* p) {
    uint32_t a = (uint32_t)__cvta_generic_to_shared(p);
    asm volatile("ldmatrix.sync.aligned.m8n8.x4.shared.b16 {%0,%1,%2,%3}, [%4];"
                 : "=r"(r[0]), "=r"(r[1]), "=r"(r[2]), "=r"(r[3]) : "r"(a));
}
__device__ __forceinline__ void ldm_x4_t(uint32_t* r, const void* p) {
    uint32_t a = (uint32_t)__cvta_generic_to_shared(p);
    asm volatile("ldmatrix.sync.aligned.m8n8.x4.trans.shared.b16 {%0,%1,%2,%3}, [%4];"
                 : "=r"(r[0]), "=r"(r[1]), "=r"(r[2]), "=r"(r[3]) : "r"(a));
}
__device__ __forceinline__ void ldm_x2_t(uint32_t* r, const void* p) {
    uint32_t a = (uint32_t)__cvta_generic_to_shared(p);
    asm volatile("ldmatrix.sync.aligned.m8n8.x2.trans.shared.b16 {%0,%1}, [%2];"
                 : "=r"(r[0]), "=r"(r[1]) : "r"(a));
}

__device__ __forceinline__ void mma_f16(float* d, const uint32_t* a, const uint32_t* b) {
    asm volatile("mma.sync.aligned.m16n8k16.row.col.f32.f16.f16.f32 "
                 "{%0,%1,%2,%3}, {%4,%5,%6,%7}, {%8,%9}, {%0,%1,%2,%3};"
                 : "+f"(d[0]), "+f"(d[1]), "+f"(d[2]), "+f"(d[3])
                 : "r"(a[0]), "r"(a[1]), "r"(a[2]), "r"(a[3]), "r"(b[0]), "r"(b[1]));
}

__device__ __forceinline__ void cp16(void* dst, const void* src) {
    uint32_t d = (uint32_t)__cvta_generic_to_shared(dst);
    asm volatile("cp.async.cg.shared.global [%0], [%1], 16;" :: "r"(d), "l"(src));
}
__device__ __forceinline__ void cp_commit() { asm volatile("cp.async.commit_group;"); }
template <int NN>
__device__ __forceinline__ void cp_wait() { asm volatile("cp.async.wait_group %0;" :: "n"(NN)); }

__device__ __forceinline__ uint32_t packh2(float a, float b) {
    half2 h = __floats2half2_rn(a, b);
    return *(uint32_t*)&h;
}

// ---------------------------------------------------------------------------
// Fused prepass: x/qkv_w/proj_w fp32->fp16 + rope table, ONE launch.
// ---------------------------------------------------------------------------
#define PRE_NX  (TOKENS * C_ / 4)
#define PRE_NW1 (C_ * 3 * C_ / 4)
#define PRE_NW2 (C_ * C_ / 4)
#define PRE_NT  (N_ * HD_)
#define PRE_TOTAL (PRE_NX + PRE_NW1 + PRE_NW2 + PRE_NT)

__global__ __launch_bounds__(256)
void prepass_kernel(const float* __restrict__ x, const float* __restrict__ qkv_w,
                    const float* __restrict__ proj_w,
                    __half* __restrict__ xh, __half* __restrict__ wqkvh,
                    __half* __restrict__ wprojh, float2* __restrict__ tab)
{
    int i = blockIdx.x * 256 + threadIdx.x;
    if (i < PRE_NX + PRE_NW1 + PRE_NW2) {
        const float* src;
        __half* dst;
        int j = i;
        if (j < PRE_NX) { src = x; dst = xh; }
        else if (j < PRE_NX + PRE_NW1) { j -= PRE_NX; src = qkv_w; dst = wqkvh; }
        else { j -= PRE_NX + PRE_NW1; src = proj_w; dst = wprojh; }
        float4 v = ((const float4*)src)[j];
        ((half2*)dst)[j * 2]     = __floats2half2_rn(v.x, v.y);
        ((half2*)dst)[j * 2 + 1] = __floats2half2_rn(v.z, v.w);
    } else {
        int j = i - (PRE_NX + PRE_NW1 + PRE_NW2);
        int n = j >> 6, c = j & 63;
        const bool lo = (c < 32);
        const int j0 = c & 31;
        const float LOG2_THETA = 13.28771237954945f;
        float f = exp2f(-(float)(j0 & 15) * (1.0f / 16.0f) * LOG2_THETA);
        float t = lo ? (float)(n >> 5) : (float)(n & 31);
        float s, co;
        sincosf(t * f, &s, &co);
        tab[j] = make_float2(co, s);
    }
}

// ---------------------------------------------------------------------------
// fp16 HMMA GEMM, CTA 128x128, BK=64, 128 threads (4 warps, 2x2 of 64x64).
// 2-stage cp.async pipeline, 3 CTAs/SM, regs capped at 170. (unchanged R13)
// ---------------------------------------------------------------------------
template <int MODE>
__global__ __launch_bounds__(128, 3)
void gemm_f16_kernel(const __half* __restrict__ A, const __half* __restrict__ Bm,
                     const float* __restrict__ bias, float* __restrict__ Cf,
                     __half* __restrict__ Ch,
                     const float* __restrict__ q_gamma,
                     const float* __restrict__ k_gamma,
                     const float2* __restrict__ ropetab,
                     int M, int N, int K)
{
    extern __shared__ char sraw[];
    __half (*As)[128][72] = (__half(*)[128][72])sraw;
    __half (*Bs)[64][136] = (__half(*)[64][136])(sraw + 2 * 128 * 72 * 2);

    const int tid  = threadIdx.x;
    const int warp = tid >> 5, lane = tid & 31;
    const int wm = warp >> 1, wn = warp & 1;
    const int g = lane >> 2, tq = lane & 3;
    const int row0 = blockIdx.y * 128;
    const int col0 = blockIdx.x * 128;
    const int KT = K / 64;

#define LOAD_STAGE(S, KT0)                                                          \
    {                                                                               \
        _Pragma("unroll")                                                           \
        for (int i = 0; i < 8; i++) {                                               \
            int f = tid + i * 128;                                                  \
            int r_ = f >> 3, u_ = f & 7;                                            \
            cp16(&As[S][r_][u_ * 8],                                                \
                 A + (size_t)(row0 + r_) * K + (KT0) * 64 + u_ * 8);                \
            int br_ = f >> 4, nb_ = f & 15;                                         \
            cp16(&Bs[S][br_][nb_ * 8],                                              \
                 Bm + (size_t)((KT0) * 64 + br_) * N + col0 + nb_ * 8);             \
        }                                                                           \
        cp_commit();                                                                \
    }

    float acc[4][8][4];
#pragma unroll
    for (int a = 0; a < 4; a++)
#pragma unroll
        for (int b = 0; b < 8; b++)
#pragma unroll
            for (int c = 0; c < 4; c++) acc[a][b][c] = 0.0f;

    LOAD_STAGE(0, 0);
    LOAD_STAGE(1, 1);

    for (int kt = 0; kt < KT; kt++) {
        const int s = kt & 1;
        if (kt + 1 < KT) { cp_wait<1>(); } else { cp_wait<0>(); }
        __syncthreads();

#pragma unroll
        for (int ks = 0; ks < 4; ks++) {
            const int k0 = ks * 16;
            uint32_t afr[4][4];
#pragma unroll
            for (int mt = 0; mt < 4; mt++)
                ldm_x4(afr[mt], &As[s][wm * 64 + mt * 16 + (lane & 15)]
                                     [k0 + (lane >> 4) * 8]);
#pragma unroll
            for (int nt2 = 0; nt2 < 4; nt2++) {
                uint32_t r4[4];
                ldm_x4_t(r4, &Bs[s][k0 + (lane & 15)]
                                   [wn * 64 + nt2 * 16 + (lane >> 4) * 8]);
                uint32_t b0[2] = { r4[0], r4[1] };
                uint32_t b1[2] = { r4[2], r4[3] };
#pragma unroll
                for (int mt = 0; mt < 4; mt++) {
                    mma_f16(acc[mt][nt2 * 2],     afr[mt], b0);
                    mma_f16(acc[mt][nt2 * 2 + 1], afr[mt], b1);
                }
            }
        }

        if (kt + 2 < KT) {
            __syncthreads();
            LOAD_STAGE(s, kt + 2);
        }
    }

    if (MODE == 0) {
#pragma unroll
        for (int mt = 0; mt < 4; mt++) {
            const int r = row0 + wm * 64 + mt * 16 + g;
#pragma unroll
            for (int nt = 0; nt < 8; nt++) {
                const int c = col0 + wn * 64 + nt * 8 + 2 * tq;
                const float b0 = bias[c], b1 = bias[c + 1];
                float2 v0 = make_float2(acc[mt][nt][0] + b0, acc[mt][nt][1] + b1);
                float2 v1 = make_float2(acc[mt][nt][2] + b0, acc[mt][nt][3] + b1);
                *(float2*)&Cf[(size_t)r * N + c]       = v0;
                *(float2*)&Cf[(size_t)(r + 8) * N + c] = v1;
            }
        }
    } else {
        const int gc  = col0 + wn * 64;
        const int sec = gc >> 10;            // 0=q, 1=k, 2=v
        float br[8][2], gr[8][2];
        const float* gam = (sec == 1) ? k_gamma : q_gamma;
#pragma unroll
        for (int nt = 0; nt < 8; nt++) {
            const int cc = nt * 8 + 2 * tq;
            br[nt][0] = bias[gc + cc];
            br[nt][1] = bias[gc + cc + 1];
            if (sec < 2) {
                gr[nt][0] = gam[cc];
                gr[nt][1] = gam[cc + 1];
            }
        }

#pragma unroll
        for (int mt = 0; mt < 4; mt++) {
#pragma unroll
            for (int rh = 0; rh < 2; rh++) {
                const int tok = row0 + wm * 64 + mt * 16 + g + rh * 8;
                __half* outp = Ch + (size_t)tok * TOKSTRIDE + gc;
                float vv[8][2];
#pragma unroll
                for (int nt = 0; nt < 8; nt++) {
                    vv[nt][0] = acc[mt][nt][rh * 2]     + br[nt][0];
                    vv[nt][1] = acc[mt][nt][rh * 2 + 1] + br[nt][1];
                }
                if (sec == 2) {
#pragma unroll
                    for (int nt = 0; nt < 8; nt++)
                        *(half2*)&outp[nt * 8 + 2 * tq] =
                            __floats2half2_rn(vv[nt][0], vv[nt][1]);
                    continue;
                }
                float ss = 0.0f;
#pragma unroll
                for (int nt = 0; nt < 8; nt++)
                    ss += vv[nt][0] * vv[nt][0] + vv[nt][1] * vv[nt][1];
                ss += __shfl_xor_sync(0xffffffffu, ss, 1);
                ss += __shfl_xor_sync(0xffffffffu, ss, 2);
                const float inv = rsqrtf(ss * (1.0f / 64.0f) + 1e-6f);
#pragma unroll
                for (int nt = 0; nt < 8; nt++) {
                    vv[nt][0] *= inv * gr[nt][0];
                    vv[nt][1] *= inv * gr[nt][1];
                }
                const int n = tok & (N_ - 1);
                const float2* tabn = ropetab + (size_t)n * HD_;
#pragma unroll
                for (int nt = 0; nt < 4; nt++) {
                    const int cc = nt * 8 + 2 * tq;
                    float2 t0 = tabn[cc], t1 = tabn[cc + 1];
                    float2 u0 = tabn[cc + 32], u1 = tabn[cc + 33];
                    float lo0 = vv[nt][0] * t0.x - vv[nt + 4][0] * t0.y;
                    float lo1 = vv[nt][1] * t1.x - vv[nt + 4][1] * t1.y;
                    float hi0 = vv[nt + 4][0] * u0.x + vv[nt][0] * u0.y;
                    float hi1 = vv[nt + 4][1] * u1.x + vv[nt][1] * u1.y;
                    *(half2*)&outp[cc]      = __floats2half2_rn(lo0, lo1);
                    *(half2*)&outp[cc + 32] = __floats2half2_rn(hi0, hi1);
                }
            }
        }
    }
#undef LOAD_STAGE
}

#define GEMM_SMEM ((2 * 128 * 72 + 2 * 64 * 136) * 2)   // 71680

// ---------------------------------------------------------------------------
// fp16 HMMA flash attention.
// CTA: 256 queries x 64-kv tiles, 8 warps (256 thr), warp = 32 q rows
// (4:1 MMA:LDSM preserved). KV fetched 4x per head instead of 8x.
// fp32 exp + ones-column MMA row-sums (R15 numerics). 1 CTA/SM, 8 warps.
// ---------------------------------------------------------------------------
struct FSmem {
    __half Qs[256][72];      // pre-scaled Q (staging)
    __half Ks[3][64][72];
    __half Vs[3][64][72];    // cols 64..71: [1,0,0,0,0,0,0,0] ones-column
};

__global__ __launch_bounds__(256, 1)
void flash_f16_kernel(const __half* __restrict__ qkvh, __half* __restrict__ out)
{
    extern __shared__ char sm_raw[];
    FSmem& sm = *reinterpret_cast<FSmem*>(sm_raw);

    const int tid  = threadIdx.x;
    const int warp = tid >> 5, lane = tid & 31;
    const int g = lane >> 2, tq = lane & 3;
    const int qtile = blockIdx.x;        // 0..3 (256 rows each)
    const int bh = blockIdx.y;           // 0..511
    const int b = bh >> 4, h = bh & 15;
    const int m0 = warp * 32;            // warp covers rows m0..m0+31

    const __half* qbase = qkvh + (size_t)b * N_ * TOKSTRIDE + h * HD_;
    const __half* kbase = qbase + C_;
    const __half* vbase = qbase + 2 * C_;

    const half2 hscale = __floats2half2_rn(0.125f, 0.125f);
    for (int i = tid; i < 4096; i += 256) {     // 256 rows x 16 quads
        int r = i >> 4, d4 = (i & 15) * 4;
        half2 a = *(const half2*)(qbase + (size_t)(qtile * 256 + r) * TOKSTRIDE + d4);
        half2 c = *(const half2*)(qbase + (size_t)(qtile * 256 + r) * TOKSTRIDE + d4 + 2);
        *(half2*)&sm.Qs[r][d4]     = __hmul2(a, hscale);
        *(half2*)&sm.Qs[r][d4 + 2] = __hmul2(c, hscale);
    }

    // Ones-column init: Vs[buf][r][64] = 1.0h, [65..71] = 0.
    for (int i = tid; i < 3 * 64; i += 256) {
        int bufi = i >> 6, r = i & 63;
        uint4 pad;
        pad.x = 0x00003C00u;   // halves {1.0, 0.0}
        pad.y = 0u; pad.z = 0u; pad.w = 0u;
        *(uint4*)&sm.Vs[bufi][r][64] = pad;
    }

#define LOAD_KV(BUF, KT0)                                                           \
    {                                                                               \
        for (int i = tid; i < 1024; i += 256) {                                     \
            int r_ = i >> 3, u_ = (i & 7) * 8;                                      \
            if (i < 512)                                                            \
                cp16(&sm.Ks[BUF][r_][u_],                                           \
                     kbase + (size_t)((KT0) * 64 + r_) * TOKSTRIDE + u_);           \
            else                                                                    \
                cp16(&sm.Vs[BUF][r_ - 64][u_],                                      \
                     vbase + (size_t)((KT0) * 64 + r_ - 64) * TOKSTRIDE + u_);      \
        }                                                                           \
        cp_commit();                                                                \
    }

    LOAD_KV(0, 0);
    LOAD_KV(1, 1);
    __syncthreads();    // Qs + ones-columns visible to all warps

    uint32_t aq[2][4][4];
#pragma unroll
    for (int mt = 0; mt < 2; mt++)
#pragma unroll
        for (int ks = 0; ks < 4; ks++)
            ldm_x4(aq[mt][ks], &sm.Qs[m0 + mt * 16 + (lane & 15)]
                                     [ks * 16 + (lane >> 4) * 8]);

    float o[2][8][4];
    float ox[2][4];          // ones-column accumulator: l lands in col 64
#pragma unroll
    for (int mt = 0; mt < 2; mt++) {
#pragma unroll
        for (int d = 0; d < 4; d++) ox[mt][d] = 0.0f;
#pragma unroll
        for (int c = 0; c < 8; c++)
#pragma unroll
            for (int d = 0; d < 4; d++) o[mt][c][d] = 0.0f;
    }

    const int ki = lane & 7, kq = lane >> 3;

    for (int kt = 0; kt < 16; kt++) {
        const int buf = kt % 3;
        if (kt + 1 < 16) { cp_wait<1>(); } else { cp_wait<0>(); }
        __syncthreads();

        if (kt + 2 < 16) { LOAD_KV((kt + 2) % 3, kt + 2); }

        // ---- S = Q @ K^T ----
        float s[2][8][4];
#pragma unroll
        for (int mt = 0; mt < 2; mt++)
#pragma unroll
            for (int c = 0; c < 8; c++)
#pragma unroll
                for (int d = 0; d < 4; d++) s[mt][c][d] = 0.0f;

#pragma unroll
        for (int ks = 0; ks < 4; ks++) {
            const int k0 = ks * 16;
#pragma unroll
            for (int nt2 = 0; nt2 < 4; nt2++) {
                uint32_t r4[4];
                ldm_x4(r4, &sm.Ks[buf][nt2 * 16 + (kq >> 1) * 8 + ki]
                                      [k0 + (kq & 1) * 8]);
                uint32_t b0[2] = { r4[0], r4[1] };
                uint32_t b1[2] = { r4[2], r4[3] };
                mma_f16(s[0][nt2 * 2],     aq[0][ks], b0);
                mma_f16(s[0][nt2 * 2 + 1], aq[0][ks], b1);
                mma_f16(s[1][nt2 * 2],     aq[1][ks], b0);
                mma_f16(s[1][nt2 * 2 + 1], aq[1][ks], b1);
            }
        }

        // ---- P = exp(s - 8) in fp32, packed to fp16 A-fragments ----
        uint32_t pa[2][4][4];
#pragma unroll
        for (int mt = 0; mt < 2; mt++)
#pragma unroll
            for (int ks = 0; ks < 4; ks++) {
                const float* s0 = s[mt][2 * ks];
                const float* s1 = s[mt][2 * ks + 1];
                pa[mt][ks][0] = packh2(__expf(s0[0] - 8.0f), __expf(s0[1] - 8.0f));
                pa[mt][ks][1] = packh2(__expf(s0[2] - 8.0f), __expf(s0[3] - 8.0f));
                pa[mt][ks][2] = packh2(__expf(s1[0] - 8.0f), __expf(s1[1] - 8.0f));
                pa[mt][ks][3] = packh2(__expf(s1[2] - 8.0f), __expf(s1[3] - 8.0f));
            }

        // ---- O += P @ V ; l accumulates in ox via ones-column ----
#pragma unroll
        for (int ks = 0; ks < 4; ks++) {
            const int k0 = ks * 16;
#pragma unroll
            for (int nt2 = 0; nt2 < 4; nt2++) {
                uint32_t r4[4];
                ldm_x4_t(r4, &sm.Vs[buf][k0 + (lane & 15)]
                                        [nt2 * 16 + (lane >> 4) * 8]);
                uint32_t b0[2] = { r4[0], r4[1] };
                uint32_t b1[2] = { r4[2], r4[3] };
                mma_f16(o[0][nt2 * 2],     pa[0][ks], b0);
                mma_f16(o[0][nt2 * 2 + 1], pa[0][ks], b1);
                mma_f16(o[1][nt2 * 2],     pa[1][ks], b0);
                mma_f16(o[1][nt2 * 2 + 1], pa[1][ks], b1);
            }
            // ones-column tile (cols 64..71)
            {
                uint32_t r2[2];
                ldm_x2_t(r2, &sm.Vs[buf][k0 + (lane & 15)][64]);
                mma_f16(ox[0], pa[0][ks], r2);
                mma_f16(ox[1], pa[1][ks], r2);
            }
        }
    }

    // ---- epilogue: l from tq=0 lanes, O /= l, store fp16 ----
#pragma unroll
    for (int mt = 0; mt < 2; mt++) {
        const float l0 = __shfl_sync(0xffffffffu, ox[mt][0], lane & 28);
        const float l1 = __shfl_sync(0xffffffffu, ox[mt][2], lane & 28);
        const float i0 = 1.0f / l0;
        const float i1 = 1.0f / l1;
        const int r = qtile * 256 + m0 + mt * 16 + g;
#pragma unroll
        for (int nt = 0; nt < 8; nt++) {
            const int c = h * 64 + nt * 8 + 2 * tq;
            *(half2*)&out[(size_t)(b * N_ + r) * C_ + c] =
                __floats2half2_rn(o[mt][nt][0] * i0, o[mt][nt][1] * i0);
            *(half2*)&out[(size_t)(b * N_ + r + 8) * C_ + c] =
                __floats2half2_rn(o[mt][nt][2] * i1, o[mt][nt][3] * i1);
        }
    }
#undef LOAD_KV
}

// ---------------------------------------------------------------------------
// Launch
// ---------------------------------------------------------------------------
extern "C" void kernel_launch(void* const* d_in, const int* in_sizes, int n_in,
                              void* d_out, int out_size)
{
    const float* x       = (const float*)d_in[0];
    const float* qkv_w   = (const float*)d_in[1];
    const float* qkv_b   = (const float*)d_in[2];
    const float* proj_w  = (const float*)d_in[3];
    const float* proj_b  = (const float*)d_in[4];
    const float* q_gamma = (const float*)d_in[5];
    const float* k_gamma = (const float*)d_in[6];
    float* out = (float*)d_out;

    void *p_xh, *p_wqkvh, *p_wprojh, *p_qkvh, *p_attnh, *p_tab;
    cudaGetSymbolAddress(&p_xh, g_xh);
    cudaGetSymbolAddress(&p_wqkvh, g_wqkvh);
    cudaGetSymbolAddress(&p_wprojh, g_wprojh);
    cudaGetSymbolAddress(&p_qkvh, g_qkvh);
    cudaGetSymbolAddress(&p_attnh, g_attnh);
    cudaGetSymbolAddress(&p_tab, g_ropetab);
    __half* xh     = (__half*)p_xh;
    __half* wqkvh  = (__half*)p_wqkvh;
    __half* wprojh = (__half*)p_wprojh;
    __half* qkvh   = (__half*)p_qkvh;
    __half* attnh  = (__half*)p_attnh;
    float2* tab    = (float2*)p_tab;

    const int flash_smem = (int)sizeof(FSmem);   // 92160
    cudaFuncSetAttribute(gemm_f16_kernel<0>,
                         cudaFuncAttributeMaxDynamicSharedMemorySize, GEMM_SMEM);
    cudaFuncSetAttribute(gemm_f16_kernel<1>,
                         cudaFuncAttributeMaxDynamicSharedMemorySize, GEMM_SMEM);
    cudaFuncSetAttribute(flash_f16_kernel,
                         cudaFuncAttributeMaxDynamicSharedMemorySize, flash_smem);

    // 0. fused prepass (fp16 conversions + rope table, single launch)
    prepass_kernel<<<PRE_TOTAL / 256, 256>>>(x, qkv_w, proj_w, xh, wqkvh, wprojh, tab);

    // 1. QKV GEMM + fused RMSNorm/RoPE epilogue (fp16 out)
    {
        dim3 grid(3 * C_ / 128, TOKENS / 128);
        gemm_f16_kernel<1><<<grid, 128, GEMM_SMEM>>>(
            xh, wqkvh, qkv_b, nullptr, qkvh, q_gamma, k_gamma, tab,
            TOKENS, 3 * C_, C_);
    }

    // 2. Flash attention (256q CTA, 8 warps, 4:1 ratio, halved KV traffic)
    {
        dim3 grid(N_ / 256, B_ * H_);
        flash_f16_kernel<<<grid, 256, flash_smem>>>(qkvh, attnh);
    }

    // 3. Output projection (fp32 out)
    {
        dim3 grid(C_ / 128, TOKENS / 128);
        gemm_f16_kernel<0><<<grid, 128, GEMM_SMEM>>>(
            attnh, wprojh, proj_b, out, nullptr, nullptr, nullptr, nullptr,
            TOKENS, C_, C_);
    }
}

// round 17
// speedup vs baseline: 1.0621x; 1.0621x over previous
#include <cuda_runtime.h>
#include <cuda_fp16.h>
#include <math.h>
#include <stdint.h>

#define B_  32
#define N_  1024
#define C_  1024
#define H_  16
#define HD_ 64
#define TOKENS (B_ * N_)        // 32768
#define TOKSTRIDE 3072

// Scratch (static device globals; no runtime allocation)
__device__ __half g_xh[(size_t)TOKENS * C_];           // fp16 x
__device__ __half g_wqkvh[(size_t)C_ * 3 * C_];        // fp16 qkv_w [1024][3072]
__device__ __half g_wprojh[(size_t)C_ * C_];           // fp16 proj_w [1024][1024]
__device__ __half g_qkvh[(size_t)TOKENS * TOKSTRIDE];  // fp16 q(roped)/k(roped)/v
__device__ __half g_attnh[(size_t)TOKENS * C_];        // fp16 attention output
__device__ float2 g_ropetab[(size_t)N_ * HD_];         // (cos, sin) per (n, c)

// ---------------------------------------------------------------------------
// Helpers
// ---------------------------------------------------------------------------
__device__ __forceinline__ void ldm_x4(uint32_t* r, const void* p) {
    uint32_t a = (uint32_t)__cvta_generic_to_shared(p);
    asm volatile("ldmatrix.sync.aligned.m8n8.x4.shared.b16 {%0,%1,%2,%3}, [%4];"
                 : "=r"(r[0]), "=r"(r[1]), "=r"(r[2]), "=r"(r[3]) : "r"(a));
}
__device__ __forceinline__ void ldm_x4_t(uint32_t* r, const void* p) {
    uint32_t a = (uint32_t)__cvta_generic_to_shared(p);
    asm volatile("ldmatrix.sync.aligned.m8n8.x4.trans.shared.b16 {%0,%1,%2,%3}, [%4];"
                 : "=r"(r[0]), "=r"(r[1]), "=r"(r[2]), "=r"(r[3]) : "r"(a));
}

__device__ __forceinline__ void mma_f16(float* d, const uint32_t* a, const uint32_t* b) {
    asm volatile("mma.sync.aligned.m16n8k16.row.col.f32.f16.f16.f32 "
                 "{%0,%1,%2,%3}, {%4,%5,%6,%7}, {%8,%9}, {%0,%1,%2,%3};"
                 : "+f"(d[0]), "+f"(d[1]), "+f"(d[2]), "+f"(d[3])
                 : "r"(a[0]), "r"(a[1]), "r"(a[2]), "r"(a[3]), "r"(b[0]), "r"(b[1]));
}

__device__ __forceinline__ void cp16(void* dst, const void* src) {
    uint32_t d = (uint32_t)__cvta_generic_to_shared(dst);
    asm volatile("cp.async.cg.shared.global [%0], [%1], 16;" :: "r"(d), "l"(src));
}
__device__ __forceinline__ void cp_commit() { asm volatile("cp.async.commit_group;"); }
template <int NN>
__device__ __forceinline__ void cp_wait() { asm volatile("cp.async.wait_group %0;" :: "n"(NN)); }

__device__ __forceinline__ uint32_t packh2(float a, float b) {
    half2 h = __floats2half2_rn(a, b);
    return *(uint32_t*)&h;
}
__device__ __forceinline__ void stcs_f2(float* p, float2 v) {
    asm volatile("st.global.cs.v2.f32 [%0], {%1, %2};"
                 :: "l"(p), "f"(v.x), "f"(v.y) : "memory");
}

// ---------------------------------------------------------------------------
// Fused prepass: x/qkv_w/proj_w fp32->fp16 + rope table, ONE launch.
// ---------------------------------------------------------------------------
#define PRE_NX  (TOKENS * C_ / 4)
#define PRE_NW1 (C_ * 3 * C_ / 4)
#define PRE_NW2 (C_ * C_ / 4)
#define PRE_NT  (N_ * HD_)
#define PRE_TOTAL (PRE_NX + PRE_NW1 + PRE_NW2 + PRE_NT)

__global__ __launch_bounds__(256)
void prepass_kernel(const float* __restrict__ x, const float* __restrict__ qkv_w,
                    const float* __restrict__ proj_w,
                    __half* __restrict__ xh, __half* __restrict__ wqkvh,
                    __half* __restrict__ wprojh, float2* __restrict__ tab)
{
    int i = blockIdx.x * 256 + threadIdx.x;
    if (i < PRE_NX + PRE_NW1 + PRE_NW2) {
        const float* src;
        __half* dst;
        int j = i;
        if (j < PRE_NX) { src = x; dst = xh; }
        else if (j < PRE_NX + PRE_NW1) { j -= PRE_NX; src = qkv_w; dst = wqkvh; }
        else { j -= PRE_NX + PRE_NW1; src = proj_w; dst = wprojh; }
        float4 v = ((const float4*)src)[j];
        ((half2*)dst)[j * 2]     = __floats2half2_rn(v.x, v.y);
        ((half2*)dst)[j * 2 + 1] = __floats2half2_rn(v.z, v.w);
    } else {
        int j = i - (PRE_NX + PRE_NW1 + PRE_NW2);
        int n = j >> 6, c = j & 63;
        const bool lo = (c < 32);
        const int j0 = c & 31;
        const float LOG2_THETA = 13.28771237954945f;
        float f = exp2f(-(float)(j0 & 15) * (1.0f / 16.0f) * LOG2_THETA);
        float t = lo ? (float)(n >> 5) : (float)(n & 31);
        float s, co;
        sincosf(t * f, &s, &co);
        tab[j] = make_float2(co, s);
    }
}

// ---------------------------------------------------------------------------
// fp16 HMMA GEMM, CTA 128x128, BK=64, 128 threads (4 warps, 2x2 of 64x64).
// 2-stage cp.async pipeline, 3 CTAs/SM, regs capped at 170.
// MODE 0: C(fp32) = A@B + bias (streaming stores — output never re-read).
// MODE 1: QKV fused epilogue -> fp16 out with RMSNorm+RoPE on q,k sections.
// ---------------------------------------------------------------------------
template <int MODE>
__global__ __launch_bounds__(128, 3)
void gemm_f16_kernel(const __half* __restrict__ A, const __half* __restrict__ Bm,
                     const float* __restrict__ bias, float* __restrict__ Cf,
                     __half* __restrict__ Ch,
                     const float* __restrict__ q_gamma,
                     const float* __restrict__ k_gamma,
                     const float2* __restrict__ ropetab,
                     int M, int N, int K)
{
    extern __shared__ char sraw[];
    __half (*As)[128][72] = (__half(*)[128][72])sraw;
    __half (*Bs)[64][136] = (__half(*)[64][136])(sraw + 2 * 128 * 72 * 2);

    const int tid  = threadIdx.x;
    const int warp = tid >> 5, lane = tid & 31;
    const int wm = warp >> 1, wn = warp & 1;
    const int g = lane >> 2, tq = lane & 3;
    const int row0 = blockIdx.y * 128;
    const int col0 = blockIdx.x * 128;
    const int KT = K / 64;

#define LOAD_STAGE(S, KT0)                                                          \
    {                                                                               \
        _Pragma("unroll")                                                           \
        for (int i = 0; i < 8; i++) {                                               \
            int f = tid + i * 128;                                                  \
            int r_ = f >> 3, u_ = f & 7;                                            \
            cp16(&As[S][r_][u_ * 8],                                                \
                 A + (size_t)(row0 + r_) * K + (KT0) * 64 + u_ * 8);                \
            int br_ = f >> 4, nb_ = f & 15;                                         \
            cp16(&Bs[S][br_][nb_ * 8],                                              \
                 Bm + (size_t)((KT0) * 64 + br_) * N + col0 + nb_ * 8);             \
        }                                                                           \
        cp_commit();                                                                \
    }

    float acc[4][8][4];
#pragma unroll
    for (int a = 0; a < 4; a++)
#pragma unroll
        for (int b = 0; b < 8; b++)
#pragma unroll
            for (int c = 0; c < 4; c++) acc[a][b][c] = 0.0f;

    LOAD_STAGE(0, 0);
    LOAD_STAGE(1, 1);

    for (int kt = 0; kt < KT; kt++) {
        const int s = kt & 1;
        if (kt + 1 < KT) { cp_wait<1>(); } else { cp_wait<0>(); }
        __syncthreads();

#pragma unroll
        for (int ks = 0; ks < 4; ks++) {
            const int k0 = ks * 16;
            uint32_t afr[4][4];
#pragma unroll
            for (int mt = 0; mt < 4; mt++)
                ldm_x4(afr[mt], &As[s][wm * 64 + mt * 16 + (lane & 15)]
                                     [k0 + (lane >> 4) * 8]);
#pragma unroll
            for (int nt2 = 0; nt2 < 4; nt2++) {
                uint32_t r4[4];
                ldm_x4_t(r4, &Bs[s][k0 + (lane & 15)]
                                   [wn * 64 + nt2 * 16 + (lane >> 4) * 8]);
                uint32_t b0[2] = { r4[0], r4[1] };
                uint32_t b1[2] = { r4[2], r4[3] };
#pragma unroll
                for (int mt = 0; mt < 4; mt++) {
                    mma_f16(acc[mt][nt2 * 2],     afr[mt], b0);
                    mma_f16(acc[mt][nt2 * 2 + 1], afr[mt], b1);
                }
            }
        }

        if (kt + 2 < KT) {
            __syncthreads();
            LOAD_STAGE(s, kt + 2);
        }
    }

    if (MODE == 0) {
#pragma unroll
        for (int mt = 0; mt < 4; mt++) {
            const int r = row0 + wm * 64 + mt * 16 + g;
#pragma unroll
            for (int nt = 0; nt < 8; nt++) {
                const int c = col0 + wn * 64 + nt * 8 + 2 * tq;
                const float b0 = bias[c], b1 = bias[c + 1];
                float2 v0 = make_float2(acc[mt][nt][0] + b0, acc[mt][nt][1] + b1);
                float2 v1 = make_float2(acc[mt][nt][2] + b0, acc[mt][nt][3] + b1);
                stcs_f2(&Cf[(size_t)r * N + c], v0);
                stcs_f2(&Cf[(size_t)(r + 8) * N + c], v1);
            }
        }
    } else {
        const int gc  = col0 + wn * 64;
        const int sec = gc >> 10;            // 0=q, 1=k, 2=v
        float br[8][2], gr[8][2];
        const float* gam = (sec == 1) ? k_gamma : q_gamma;
#pragma unroll
        for (int nt = 0; nt < 8; nt++) {
            const int cc = nt * 8 + 2 * tq;
            br[nt][0] = bias[gc + cc];
            br[nt][1] = bias[gc + cc + 1];
            if (sec < 2) {
                gr[nt][0] = gam[cc];
                gr[nt][1] = gam[cc + 1];
            }
        }

#pragma unroll
        for (int mt = 0; mt < 4; mt++) {
#pragma unroll
            for (int rh = 0; rh < 2; rh++) {
                const int tok = row0 + wm * 64 + mt * 16 + g + rh * 8;
                __half* outp = Ch + (size_t)tok * TOKSTRIDE + gc;
                float vv[8][2];
#pragma unroll
                for (int nt = 0; nt < 8; nt++) {
                    vv[nt][0] = acc[mt][nt][rh * 2]     + br[nt][0];
                    vv[nt][1] = acc[mt][nt][rh * 2 + 1] + br[nt][1];
                }
                if (sec == 2) {
#pragma unroll
                    for (int nt = 0; nt < 8; nt++)
                        *(half2*)&outp[nt * 8 + 2 * tq] =
                            __floats2half2_rn(vv[nt][0], vv[nt][1]);
                    continue;
                }
                float ss = 0.0f;
#pragma unroll
                for (int nt = 0; nt < 8; nt++)
                    ss += vv[nt][0] * vv[nt][0] + vv[nt][1] * vv[nt][1];
                ss += __shfl_xor_sync(0xffffffffu, ss, 1);
                ss += __shfl_xor_sync(0xffffffffu, ss, 2);
                const float inv = rsqrtf(ss * (1.0f / 64.0f) + 1e-6f);
#pragma unroll
                for (int nt = 0; nt < 8; nt++) {
                    vv[nt][0] *= inv * gr[nt][0];
                    vv[nt][1] *= inv * gr[nt][1];
                }
                const int n = tok & (N_ - 1);
                const float2* tabn = ropetab + (size_t)n * HD_;
#pragma unroll
                for (int nt = 0; nt < 4; nt++) {
                    const int cc = nt * 8 + 2 * tq;
                    float2 t0 = tabn[cc], t1 = tabn[cc + 1];
                    float2 u0 = tabn[cc + 32], u1 = tabn[cc + 33];
                    float lo0 = vv[nt][0] * t0.x - vv[nt + 4][0] * t0.y;
                    float lo1 = vv[nt][1] * t1.x - vv[nt + 4][1] * t1.y;
                    float hi0 = vv[nt + 4][0] * u0.x + vv[nt][0] * u0.y;
                    float hi1 = vv[nt + 4][1] * u1.x + vv[nt][1] * u1.y;
                    *(half2*)&outp[cc]      = __floats2half2_rn(lo0, lo1);
                    *(half2*)&outp[cc + 32] = __floats2half2_rn(hi0, hi1);
                }
            }
        }
    }
#undef LOAD_STAGE
}

#define GEMM_SMEM ((2 * 128 * 72 + 2 * 64 * 136) * 2)   // 71680

// ---------------------------------------------------------------------------
// fp16 HMMA flash attention (R13 champion config).
// fixed-max softmax (fp32 exp), register-resident P, hoisted Q fragments,
// 3-stage KV ring, 1 barrier/iter.
// CTA: 128 queries x 64-kv tiles. 4 warps, warp = 32 q rows. 2 CTAs/SM.
// ---------------------------------------------------------------------------
struct FSmem {
    __half Qs[128][72];      // pre-scaled Q (staging)
    __half Ks[3][64][72];
    __half Vs[3][64][72];
};

__global__ __launch_bounds__(128, 2)
void flash_f16_kernel(const __half* __restrict__ qkvh, __half* __restrict__ out)
{
    extern __shared__ char sm_raw[];
    FSmem& sm = *reinterpret_cast<FSmem*>(sm_raw);

    const int tid  = threadIdx.x;
    const int warp = tid >> 5, lane = tid & 31;
    const int g = lane >> 2, tq = lane & 3;
    const int qtile = blockIdx.x;        // 0..7 (128 rows each)
    const int bh = blockIdx.y;           // 0..511
    const int b = bh >> 4, h = bh & 15;
    const int m0 = warp * 32;            // warp covers rows m0..m0+31

    const __half* qbase = qkvh + (size_t)b * N_ * TOKSTRIDE + h * HD_;
    const __half* kbase = qbase + C_;
    const __half* vbase = qbase + 2 * C_;

    const half2 hscale = __floats2half2_rn(0.125f, 0.125f);
    for (int i = tid; i < 2048; i += 128) {     // 128 rows x 16 quads
        int r = i >> 4, d4 = (i & 15) * 4;
        half2 a = *(const half2*)(qbase + (size_t)(qtile * 128 + r) * TOKSTRIDE + d4);
        half2 c = *(const half2*)(qbase + (size_t)(qtile * 128 + r) * TOKSTRIDE + d4 + 2);
        *(half2*)&sm.Qs[r][d4]     = __hmul2(a, hscale);
        *(half2*)&sm.Qs[r][d4 + 2] = __hmul2(c, hscale);
    }

#define LOAD_KV(BUF, KT0)                                                           \
    {                                                                               \
        for (int i = tid; i < 1024; i += 128) {                                     \
            int r_ = i >> 3, u_ = (i & 7) * 8;                                      \
            if (i < 512)                                                            \
                cp16(&sm.Ks[BUF][r_][u_],                                           \
                     kbase + (size_t)((KT0) * 64 + r_) * TOKSTRIDE + u_);           \
            else                                                                    \
                cp16(&sm.Vs[BUF][r_ - 64][u_],                                      \
                     vbase + (size_t)((KT0) * 64 + r_ - 64) * TOKSTRIDE + u_);      \
        }                                                                           \
        cp_commit();                                                                \
    }

    LOAD_KV(0, 0);
    LOAD_KV(1, 1);
    __syncthreads();    // Qs visible to all warps

    // Hoist Q fragments: aq[mt][ks], mt = m-tile (16 rows), ks = k-chunk
    uint32_t aq[2][4][4];
#pragma unroll
    for (int mt = 0; mt < 2; mt++)
#pragma unroll
        for (int ks = 0; ks < 4; ks++)
            ldm_x4(aq[mt][ks], &sm.Qs[m0 + mt * 16 + (lane & 15)]
                                     [ks * 16 + (lane >> 4) * 8]);

    float o[2][8][4];
    float lr[2][2];
#pragma unroll
    for (int mt = 0; mt < 2; mt++) {
        lr[mt][0] = lr[mt][1] = 0.0f;
#pragma unroll
        for (int c = 0; c < 8; c++)
#pragma unroll
            for (int d = 0; d < 4; d++) o[mt][c][d] = 0.0f;
    }

    const int ki = lane & 7, kq = lane >> 3;

    for (int kt = 0; kt < 16; kt++) {
        const int buf = kt % 3;
        if (kt + 1 < 16) { cp_wait<1>(); } else { cp_wait<0>(); }
        __syncthreads();    // stage kt ready; stage (kt+2)%3 free

        if (kt + 2 < 16) { LOAD_KV((kt + 2) % 3, kt + 2); }

        // ---- S = Q @ K^T (each K ldsm feeds 4 MMAs) ----
        float s[2][8][4];
#pragma unroll
        for (int mt = 0; mt < 2; mt++)
#pragma unroll
            for (int c = 0; c < 8; c++)
#pragma unroll
                for (int d = 0; d < 4; d++) s[mt][c][d] = 0.0f;

#pragma unroll
        for (int ks = 0; ks < 4; ks++) {
            const int k0 = ks * 16;
#pragma unroll
            for (int nt2 = 0; nt2 < 4; nt2++) {
                uint32_t r4[4];
                ldm_x4(r4, &sm.Ks[buf][nt2 * 16 + (kq >> 1) * 8 + ki]
                                      [k0 + (kq & 1) * 8]);
                uint32_t b0[2] = { r4[0], r4[1] };
                uint32_t b1[2] = { r4[2], r4[3] };
                mma_f16(s[0][nt2 * 2],     aq[0][ks], b0);
                mma_f16(s[0][nt2 * 2 + 1], aq[0][ks], b1);
                mma_f16(s[1][nt2 * 2],     aq[1][ks], b0);
                mma_f16(s[1][nt2 * 2 + 1], aq[1][ks], b1);
            }
        }

        // ---- fixed-max softmax: P = exp(s - 8), l += sum ----
#pragma unroll
        for (int mt = 0; mt < 2; mt++)
#pragma unroll
            for (int hf = 0; hf < 2; hf++) {
                float rs = 0.0f;
#pragma unroll
                for (int nt = 0; nt < 8; nt++) {
                    float e0 = __expf(s[mt][nt][hf * 2]     - 8.0f);
                    float e1 = __expf(s[mt][nt][hf * 2 + 1] - 8.0f);
                    s[mt][nt][hf * 2] = e0; s[mt][nt][hf * 2 + 1] = e1;
                    rs += e0 + e1;
                }
                rs += __shfl_xor_sync(0xffffffffu, rs, 1);
                rs += __shfl_xor_sync(0xffffffffu, rs, 2);
                lr[mt][hf] += rs;
            }

        // ---- pack P into A-fragments (register-resident) ----
        uint32_t pa[2][4][4];
#pragma unroll
        for (int mt = 0; mt < 2; mt++)
#pragma unroll
            for (int ks = 0; ks < 4; ks++) {
                pa[mt][ks][0] = packh2(s[mt][2 * ks][0],     s[mt][2 * ks][1]);
                pa[mt][ks][1] = packh2(s[mt][2 * ks][2],     s[mt][2 * ks][3]);
                pa[mt][ks][2] = packh2(s[mt][2 * ks + 1][0], s[mt][2 * ks + 1][1]);
                pa[mt][ks][3] = packh2(s[mt][2 * ks + 1][2], s[mt][2 * ks + 1][3]);
            }

        // ---- O += P @ V (each V ldsm feeds 4 MMAs) ----
#pragma unroll
        for (int ks = 0; ks < 4; ks++) {
            const int k0 = ks * 16;
#pragma unroll
            for (int nt2 = 0; nt2 < 4; nt2++) {
                uint32_t r4[4];
                ldm_x4_t(r4, &sm.Vs[buf][k0 + (lane & 15)]
                                        [nt2 * 16 + (lane >> 4) * 8]);
                uint32_t b0[2] = { r4[0], r4[1] };
                uint32_t b1[2] = { r4[2], r4[3] };
                mma_f16(o[0][nt2 * 2],     pa[0][ks], b0);
                mma_f16(o[0][nt2 * 2 + 1], pa[0][ks], b1);
                mma_f16(o[1][nt2 * 2],     pa[1][ks], b0);
                mma_f16(o[1][nt2 * 2 + 1], pa[1][ks], b1);
            }
        }
    }

    // ---- epilogue: O /= l, store fp16 ----
#pragma unroll
    for (int mt = 0; mt < 2; mt++) {
        const float i0 = 1.0f / lr[mt][0];
        const float i1 = 1.0f / lr[mt][1];
        const int r = qtile * 128 + m0 + mt * 16 + g;
#pragma unroll
        for (int nt = 0; nt < 8; nt++) {
            const int c = h * 64 + nt * 8 + 2 * tq;
            *(half2*)&out[(size_t)(b * N_ + r) * C_ + c] =
                __floats2half2_rn(o[mt][nt][0] * i0, o[mt][nt][1] * i0);
            *(half2*)&out[(size_t)(b * N_ + r + 8) * C_ + c] =
                __floats2half2_rn(o[mt][nt][2] * i1, o[mt][nt][3] * i1);
        }
    }
#undef LOAD_KV
}

// ---------------------------------------------------------------------------
// Launch
// ---------------------------------------------------------------------------
extern "C" void kernel_launch(void* const* d_in, const int* in_sizes, int n_in,
                              void* d_out, int out_size)
{
    const float* x       = (const float*)d_in[0];
    const float* qkv_w   = (const float*)d_in[1];
    const float* qkv_b   = (const float*)d_in[2];
    const float* proj_w  = (const float*)d_in[3];
    const float* proj_b  = (const float*)d_in[4];
    const float* q_gamma = (const float*)d_in[5];
    const float* k_gamma = (const float*)d_in[6];
    float* out = (float*)d_out;

    void *p_xh, *p_wqkvh, *p_wprojh, *p_qkvh, *p_attnh, *p_tab;
    cudaGetSymbolAddress(&p_xh, g_xh);
    cudaGetSymbolAddress(&p_wqkvh, g_wqkvh);
    cudaGetSymbolAddress(&p_wprojh, g_wprojh);
    cudaGetSymbolAddress(&p_qkvh, g_qkvh);
    cudaGetSymbolAddress(&p_attnh, g_attnh);
    cudaGetSymbolAddress(&p_tab, g_ropetab);
    __half* xh     = (__half*)p_xh;
    __half* wqkvh  = (__half*)p_wqkvh;
    __half* wprojh = (__half*)p_wprojh;
    __half* qkvh   = (__half*)p_qkvh;
    __half* attnh  = (__half*)p_attnh;
    float2* tab    = (float2*)p_tab;

    const int flash_smem = (int)sizeof(FSmem);   // 73728
    cudaFuncSetAttribute(gemm_f16_kernel<0>,
                         cudaFuncAttributeMaxDynamicSharedMemorySize, GEMM_SMEM);
    cudaFuncSetAttribute(gemm_f16_kernel<1>,
                         cudaFuncAttributeMaxDynamicSharedMemorySize, GEMM_SMEM);
    cudaFuncSetAttribute(flash_f16_kernel,
                         cudaFuncAttributeMaxDynamicSharedMemorySize, flash_smem);

    // 0. fused prepass (fp16 conversions + rope table, single launch)
    prepass_kernel<<<PRE_TOTAL / 256, 256>>>(x, qkv_w, proj_w, xh, wqkvh, wprojh, tab);

    // 1. QKV GEMM + fused RMSNorm/RoPE epilogue (fp16 out)
    {
        dim3 grid(3 * C_ / 128, TOKENS / 128);
        gemm_f16_kernel<1><<<grid, 128, GEMM_SMEM>>>(
            xh, wqkvh, qkv_b, nullptr, qkvh, q_gamma, k_gamma, tab,
            TOKENS, 3 * C_, C_);
    }

    // 2. Flash attention (R13 champion config)
    {
        dim3 grid(N_ / 128, B_ * H_);
        flash_f16_kernel<<<grid, 128, flash_smem>>>(qkvh, attnh);
    }

    // 3. Output projection (fp32 out, streaming stores)
    {
        dim3 grid(C_ / 128, TOKENS / 128);
        gemm_f16_kernel<0><<<grid, 128, GEMM_SMEM>>>(
            attnh, wprojh, proj_b, out, nullptr, nullptr, nullptr, nullptr,
            TOKENS, C_, C_);
    }
}